// round 16
// baseline (speedup 1.0000x reference)
#include <cuda_runtime.h>
#include <cstdint>

// _QuantumLSTMCell via warp-level mma.sync (HMMA bf16), sm_103-safe PTX.
// D[128 x 16] = x[128 x 256] @ W^T as 3 bf16 GEMMs (hi*hi + hi*lo + lo*hi),
// fp32 accum; hx tail (k 256..259) exact fp32 in epilogue.
// R16: A fragments loaded DIRECTLY from global into a 2-tile register
// double-buffer (8x LDG.64/tile, 8 full sectors per warp-instr). No cp.async,
// no wait_group, no syncwarp, no A staging smem. B split tiles in smem (R15).

#define THREADS 128
#define WARPS 4
#define ROWS_WARP 32
#define ROWS_BLK 128
#define D_COLS 256
#define NJ 16
#define NTILES 16
#define EPI_PITCH 20

__device__ __forceinline__ uint32_t cvt2(float hi, float lo) {
    uint32_t d;
    asm("cvt.rn.bf16x2.f32 %0, %1, %2;" : "=r"(d) : "f"(hi), "f"(lo));
    return d;
}
__device__ __forceinline__ float up_lo(uint32_t p) { return __uint_as_float(p << 16); }
__device__ __forceinline__ float up_hi(uint32_t p) { return __uint_as_float(p & 0xffff0000u); }

__device__ __forceinline__ void mma_bf16(float d[4], const uint32_t a[4],
                                         const uint32_t b[2]) {
    asm("mma.sync.aligned.m16n8k16.row.col.f32.bf16.bf16.f32 "
        "{%0,%1,%2,%3}, {%4,%5,%6,%7}, {%8,%9}, {%0,%1,%2,%3};"
        : "+f"(d[0]), "+f"(d[1]), "+f"(d[2]), "+f"(d[3])
        : "r"(a[0]), "r"(a[1]), "r"(a[2]), "r"(a[3]), "r"(b[0]), "r"(b[1]));
}

__device__ __forceinline__ float sigmoidf_(float x) {
    return 1.0f / (1.0f + __expf(-x));
}
__device__ __forceinline__ float tanhf_(float x) {
    return 1.0f - 2.0f / (__expf(2.0f * x) + 1.0f);
}

// load one tile's A data (2 m-tiles) for this thread: 8x LDG.64
// buf layout: [0..3] mtile0 {f00,f10,f01,f11}, [4..7] mtile1
__device__ __forceinline__ void loadA(float2 dst[8], const float* const pr[4],
                                      int t) {
    int off = t * 16;
#pragma unroll
    for (int m = 0; m < 2; m++) {
        dst[4*m + 0] = *(const float2*)(pr[2*m + 0] + off);
        dst[4*m + 1] = *(const float2*)(pr[2*m + 1] + off);
        dst[4*m + 2] = *(const float2*)(pr[2*m + 0] + off + 8);
        dst[4*m + 3] = *(const float2*)(pr[2*m + 1] + off + 8);
    }
}

// hi/lo split of one m-tile fragment (same math as R15)
__device__ __forceinline__ void split_frag(const float2 f[4],
                                           uint32_t ahi[4], uint32_t alo[4]) {
#pragma unroll
    for (int i = 0; i < 4; i++) {
        ahi[i] = cvt2(f[i].y, f[i].x);
        alo[i] = cvt2(f[i].y - up_hi(ahi[i]), f[i].x - up_lo(ahi[i]));
    }
}

__global__ void __launch_bounds__(THREADS, 6)
qlstm_mma_kernel(const float* __restrict__ x, const float* __restrict__ hx,
                 const float* __restrict__ cx,
                 const float* __restrict__ Wf, const float* __restrict__ Wi,
                 const float* __restrict__ Wu, const float* __restrict__ Wo,
                 const float* __restrict__ bf, const float* __restrict__ bi,
                 const float* __restrict__ bu, const float* __restrict__ bo,
                 const float* __restrict__ tf, const float* __restrict__ ti,
                 const float* __restrict__ tu, const float* __restrict__ to,
                 float* __restrict__ out, int B)
{
    // sB word index: ((tile*2 + split)*16 + j)*8 + pos (R15-proven layout)
    __shared__ __align__(16) uint32_t sB[NTILES * 2 * 16 * 8];      // 16 KB
    __shared__ __align__(16) float eb[WARPS * ROWS_WARP * EPI_PITCH]; // 10.2 KB
    __shared__ float hwt[NJ * 4];
    __shared__ float sphase[NJ];

    const int tid  = threadIdx.x;
    const int wid  = tid >> 5;
    const int lane = tid & 31;
    const int g    = lane >> 2;      // groupID
    const int tg   = lane & 3;       // threadID_in_group

    const int warpRow0 = blockIdx.x * ROWS_BLK + wid * ROWS_WARP;

    // ---- stage split-B weights (once per block) ----
#pragma unroll 1
    for (int idx = tid; idx < NJ * 128; idx += THREADS) {   // j x 128 k-pairs
        int j = idx >> 7, kpg = idx & 127;
        int chunk = kpg >> 3, kpl = kpg & 7;
        const float* Wj = ((j < 4) ? Wf : (j < 8) ? Wi : (j < 12) ? Wu : Wo)
                          + (j & 3) * 260;
        float w0 = Wj[2 * kpg], w1 = Wj[2 * kpg + 1];
        uint32_t hi = cvt2(w1, w0);
        uint32_t lo = cvt2(w1 - up_hi(hi), w0 - up_lo(hi));
        int pos = (kpl < 4) ? 2 * kpl : 2 * (kpl - 4) + 1;
        sB[((chunk * 2 + 0) * 16 + j) * 8 + pos] = hi;
        sB[((chunk * 2 + 1) * 16 + j) * 8 + pos] = lo;
    }
    if (tid < 64) {     // exact fp32 weights for hx tail: hwt[j*4 + k]
        int j = tid >> 2, k = tid & 3;
        const float* Wj = ((j < 4) ? Wf : (j < 8) ? Wi : (j < 12) ? Wu : Wo)
                          + (j & 3) * 260;
        hwt[tid] = Wj[256 + k];
    }
    if (tid < NJ) {
        int j = tid, gate = j >> 2, wire = j & 3;
        const float* bb = (gate == 0) ? bf : (gate == 1) ? bi
                        : (gate == 2) ? bu : bo;
        const float* tt = (gate == 0) ? tf : (gate == 1) ? ti
                        : (gate == 2) ? tu : to;
        sphase[j] = bb[wire] + tt[wire];
    }
    __syncthreads();    // the ONLY block barrier

    // ---- per-thread A row pointers (rows g, g+8, g+16, g+24; col base 2tg)
    const float* pr[4];
#pragma unroll
    for (int i = 0; i < 4; i++)
        pr[i] = x + (size_t)(warpRow0 + g + 8 * i) * D_COLS + 2 * tg;

    // ---- register double-buffer prologue ----
    float2 buf[2][8];
    loadA(buf[0], pr, 0);
    loadA(buf[1], pr, 1);

    float acc[2][2][4];
#pragma unroll
    for (int mt = 0; mt < 2; mt++)
#pragma unroll
        for (int nt = 0; nt < 2; nt++)
#pragma unroll
            for (int i = 0; i < 4; i++) acc[mt][nt][i] = 0.0f;

    // ---- main loop: compute tile t from buf[t&1], then refill with t+2 ----
#pragma unroll 2
    for (int t = 0; t < NTILES; t++) {
        uint32_t ahi[2][4], alo[2][4];
        split_frag(&buf[t & 1][0], ahi[0], alo[0]);
        split_frag(&buf[t & 1][4], ahi[1], alo[1]);

        uint32_t bhi[2][2], blo[2][2];
#pragma unroll
        for (int nt = 0; nt < 2; nt++) {
            uint2 h = *(const uint2*)&sB[((t * 2 + 0) * 16 + nt * 8 + g) * 8 + 2 * tg];
            uint2 l = *(const uint2*)&sB[((t * 2 + 1) * 16 + nt * 8 + g) * 8 + 2 * tg];
            bhi[nt][0] = h.x; bhi[nt][1] = h.y;
            blo[nt][0] = l.x; blo[nt][1] = l.y;
        }

#pragma unroll
        for (int mt = 0; mt < 2; mt++)
#pragma unroll
            for (int nt = 0; nt < 2; nt++) {
                mma_bf16(acc[mt][nt], ahi[mt], bhi[nt]);   // hi*hi
                mma_bf16(acc[mt][nt], ahi[mt], blo[nt]);   // hi*lo
                mma_bf16(acc[mt][nt], alo[mt], bhi[nt]);   // lo*hi
            }

        if (t + 2 < NTILES)
            loadA(buf[t & 1], pr, t + 2);
    }

    // ---- exchange D through warp-private smem ----
    float* eb_w = eb + wid * (ROWS_WARP * EPI_PITCH);
#pragma unroll
    for (int mt = 0; mt < 2; mt++)
#pragma unroll
        for (int nt = 0; nt < 2; nt++) {
            int r = mt * 16 + g, j = nt * 8 + 2 * tg;
            *(float2*)(eb_w + r * EPI_PITCH + j) =
                make_float2(acc[mt][nt][0], acc[mt][nt][1]);
            *(float2*)(eb_w + (r + 8) * EPI_PITCH + j) =
                make_float2(acc[mt][nt][2], acc[mt][nt][3]);
        }
    __syncwarp();

    // ---- epilogue: thread owns row = lane ----
    const int row = warpRow0 + lane;
    float4 hv  = ((const float4*)hx)[row];
    float4 cxv = ((const float4*)cx)[row];
    const float4* hw4 = (const float4*)hwt;

    float z[NJ];
#pragma unroll
    for (int j = 0; j < NJ; j++) {
        float4 w = hw4[j];
        float ang = eb_w[lane * EPI_PITCH + j] + sphase[j]
                  + hv.x * w.x + hv.y * w.y + hv.z * w.z + hv.w * w.w;
        z[j] = __cosf(ang);
    }
    float e[NJ];
#pragma unroll
    for (int gg = 0; gg < 4; gg++) {
        float z0 = z[gg*4+0], z1 = z[gg*4+1], z2 = z[gg*4+2], z3 = z[gg*4+3];
        float p01 = z0 * z1;
        e[gg*4+0] = z1 * z2 * z3;
        e[gg*4+1] = p01;
        e[gg*4+2] = p01 * z2;
        e[gg*4+3] = p01 * z2 * z3;
    }
    float cxa[4] = {cxv.x, cxv.y, cxv.z, cxv.w};
    float hn[4], cn[4];
#pragma unroll
    for (int w = 0; w < 4; w++) {
        float fv = sigmoidf_(e[0*4+w]);
        float iv = sigmoidf_(e[1*4+w]);
        float gv = tanhf_(e[2*4+w]);
        float ov = sigmoidf_(e[3*4+w]);
        float c = fv * cxa[w] + iv * gv;
        cn[w] = c;
        hn[w] = ov * tanhf_(c);
    }
    ((float4*)out)[row] = make_float4(hn[0], hn[1], hn[2], hn[3]);
    ((float4*)(out + (size_t)B * 4))[row] = make_float4(cn[0], cn[1], cn[2], cn[3]);
}

extern "C" void kernel_launch(void* const* d_in, const int* in_sizes, int n_in,
                              void* d_out, int out_size) {
    const float* x  = (const float*)d_in[0];
    const float* hx = (const float*)d_in[1];
    const float* cx = (const float*)d_in[2];
    const float* Wf = (const float*)d_in[3];
    const float* bf = (const float*)d_in[4];
    const float* Wi = (const float*)d_in[5];
    const float* bi = (const float*)d_in[6];
    const float* Wu = (const float*)d_in[7];
    const float* bu = (const float*)d_in[8];
    const float* Wo = (const float*)d_in[9];
    const float* bo = (const float*)d_in[10];
    const float* tf = (const float*)d_in[11];
    const float* ti = (const float*)d_in[12];
    const float* tu = (const float*)d_in[13];
    const float* to = (const float*)d_in[14];
    float* out = (float*)d_out;

    int B = in_sizes[0] / D_COLS;                 // 131072
    int grid = (B + ROWS_BLK - 1) / ROWS_BLK;     // 1024

    qlstm_mma_kernel<<<grid, THREADS>>>(x, hx, cx, Wf, Wi, Wu, Wo,
                                        bf, bi, bu, bo,
                                        tf, ti, tu, to, out, B);
}

// round 17
// speedup vs baseline: 1.1413x; 1.1413x over previous
#include <cuda_runtime.h>
#include <cstdint>

// _QuantumLSTMCell via warp-level mma.sync (HMMA bf16), sm_103-safe PTX.
// D[64 x 16] per CTA = x @ W^T as 3 bf16 GEMMs (hi*hi + hi*lo + lo*hi),
// fp32 accum; hx tail (k 256..259) exact fp32 in epilogue.
// R17: R15 structure with ROWS_WARP=16 (1 m-tile), grid 2048 -> 55 warps/SM
// supply, 8 CTAs/SM resident (50% occ) to cover cp.async tile-boundary waits.

#define THREADS 128
#define WARPS 4
#define ROWS_WARP 16
#define ROWS_BLK 64
#define D_COLS 256
#define NJ 16
#define TILE_K 16
#define NTILES 16
#define PITCH 20                    // floats per staged row (conflict-free)
#define STAGE_F (ROWS_WARP * PITCH) // 320

__device__ __forceinline__ uint32_t cvt2(float hi, float lo) {
    uint32_t d;
    asm("cvt.rn.bf16x2.f32 %0, %1, %2;" : "=r"(d) : "f"(hi), "f"(lo));
    return d;
}
__device__ __forceinline__ float up_lo(uint32_t p) { return __uint_as_float(p << 16); }
__device__ __forceinline__ float up_hi(uint32_t p) { return __uint_as_float(p & 0xffff0000u); }

__device__ __forceinline__ void mma_bf16(float d[4], const uint32_t a[4],
                                         const uint32_t b[2]) {
    asm("mma.sync.aligned.m16n8k16.row.col.f32.bf16.bf16.f32 "
        "{%0,%1,%2,%3}, {%4,%5,%6,%7}, {%8,%9}, {%0,%1,%2,%3};"
        : "+f"(d[0]), "+f"(d[1]), "+f"(d[2]), "+f"(d[3])
        : "r"(a[0]), "r"(a[1]), "r"(a[2]), "r"(a[3]), "r"(b[0]), "r"(b[1]));
}

__device__ __forceinline__ void cp16(unsigned dst, const void* src) {
    asm volatile("cp.async.cg.shared.global [%0], [%1], 16;" :: "r"(dst), "l"(src));
}
__device__ __forceinline__ void cp_commit() { asm volatile("cp.async.commit_group;"); }
__device__ __forceinline__ void cp_wait1() { asm volatile("cp.async.wait_group 1;"); }
__device__ __forceinline__ void cp_wait0() { asm volatile("cp.async.wait_group 0;"); }

__device__ __forceinline__ float sigmoidf_(float x) {
    return 1.0f / (1.0f + __expf(-x));
}
__device__ __forceinline__ float tanhf_(float x) {
    return 1.0f - 2.0f / (__expf(2.0f * x) + 1.0f);
}

// issue one TILE_K=16 tile (16 rows x 64 B) for this warp: 2 cp16/lane
__device__ __forceinline__ void issue_tile(unsigned xs_s, const float* xw,
                                           int lane, int tile, int slot) {
#pragma unroll
    for (int i = 0; i < 2; i++) {
        int rl = i * 8 + (lane >> 2);
        int ch = lane & 3;
        cp16(xs_s + (unsigned)((slot * STAGE_F + rl * PITCH + ch * 4) * 4),
             xw + (size_t)rl * D_COLS + tile * TILE_K + ch * 4);
    }
    cp_commit();
}

// load + hi/lo split of the m16 x k16 A fragment for this thread
__device__ __forceinline__ void load_a_frag(const float* xb, int g, int tg,
                                            uint32_t ahi[4], uint32_t alo[4]) {
    float2 f00 = *(const float2*)(xb + g * PITCH + 2 * tg);
    float2 f10 = *(const float2*)(xb + (g + 8) * PITCH + 2 * tg);
    float2 f01 = *(const float2*)(xb + g * PITCH + 2 * tg + 8);
    float2 f11 = *(const float2*)(xb + (g + 8) * PITCH + 2 * tg + 8);
    ahi[0] = cvt2(f00.y, f00.x);
    ahi[1] = cvt2(f10.y, f10.x);
    ahi[2] = cvt2(f01.y, f01.x);
    ahi[3] = cvt2(f11.y, f11.x);
    alo[0] = cvt2(f00.y - up_hi(ahi[0]), f00.x - up_lo(ahi[0]));
    alo[1] = cvt2(f10.y - up_hi(ahi[1]), f10.x - up_lo(ahi[1]));
    alo[2] = cvt2(f01.y - up_hi(ahi[2]), f01.x - up_lo(ahi[2]));
    alo[3] = cvt2(f11.y - up_hi(ahi[3]), f11.x - up_lo(ahi[3]));
}

__global__ void __launch_bounds__(THREADS, 8)
qlstm_mma_kernel(const float* __restrict__ x, const float* __restrict__ hx,
                 const float* __restrict__ cx,
                 const float* __restrict__ Wf, const float* __restrict__ Wi,
                 const float* __restrict__ Wu, const float* __restrict__ Wo,
                 const float* __restrict__ bf, const float* __restrict__ bi,
                 const float* __restrict__ bu, const float* __restrict__ bo,
                 const float* __restrict__ tf, const float* __restrict__ ti,
                 const float* __restrict__ tu, const float* __restrict__ to,
                 float* __restrict__ out, int B)
{
    // sB word index: ((tile*2 + split)*16 + j)*8 + pos (R15-proven layout)
    __shared__ __align__(16) uint32_t sB[NTILES * 2 * 16 * 8];    // 16 KB
    __shared__ __align__(16) float xs[WARPS * 2 * STAGE_F];       // 10.2 KB
    __shared__ float hwt[NJ * 4];
    __shared__ float sphase[NJ];

    const int tid  = threadIdx.x;
    const int wid  = tid >> 5;
    const int lane = tid & 31;
    const int g    = lane >> 2;      // groupID
    const int tg   = lane & 3;       // threadID_in_group

    const int warpRow0 = blockIdx.x * ROWS_BLK + wid * ROWS_WARP;
    const float* xw = x + (size_t)warpRow0 * D_COLS;

    float* xs_w = xs + wid * (2 * STAGE_F);
    unsigned xs_s = (unsigned)__cvta_generic_to_shared(xs_w);

    // ---- prologue: tiles 0,1 ----
    issue_tile(xs_s, xw, lane, 0, 0);
    issue_tile(xs_s, xw, lane, 1, 1);

    // ---- stage split-B weights (once per block) ----
#pragma unroll 1
    for (int idx = tid; idx < NJ * 128; idx += THREADS) {   // j x 128 k-pairs
        int j = idx >> 7, kpg = idx & 127;
        int chunk = kpg >> 3, kpl = kpg & 7;
        const float* Wj = ((j < 4) ? Wf : (j < 8) ? Wi : (j < 12) ? Wu : Wo)
                          + (j & 3) * 260;
        float w0 = Wj[2 * kpg], w1 = Wj[2 * kpg + 1];
        uint32_t hi = cvt2(w1, w0);
        uint32_t lo = cvt2(w1 - up_hi(hi), w0 - up_lo(hi));
        int pos = (kpl < 4) ? 2 * kpl : 2 * (kpl - 4) + 1;
        sB[((chunk * 2 + 0) * 16 + j) * 8 + pos] = hi;
        sB[((chunk * 2 + 1) * 16 + j) * 8 + pos] = lo;
    }
    if (tid < 64) {     // exact fp32 weights for hx tail: hwt[j*4 + k]
        int j = tid >> 2, k = tid & 3;
        const float* Wj = ((j < 4) ? Wf : (j < 8) ? Wi : (j < 12) ? Wu : Wo)
                          + (j & 3) * 260;
        hwt[tid] = Wj[256 + k];
    }
    if (tid < NJ) {
        int j = tid, gate = j >> 2, wire = j & 3;
        const float* bb = (gate == 0) ? bf : (gate == 1) ? bi
                        : (gate == 2) ? bu : bo;
        const float* tt = (gate == 0) ? tf : (gate == 1) ? ti
                        : (gate == 2) ? tu : to;
        sphase[j] = bb[wire] + tt[wire];
    }
    __syncthreads();    // the ONLY block barrier

    float acc[2][4];
#pragma unroll
    for (int nt = 0; nt < 2; nt++)
#pragma unroll
        for (int i = 0; i < 4; i++) acc[nt][i] = 0.0f;

    // ---- warp-private pipelined main loop ----
#pragma unroll 1
    for (int t = 0; t < NTILES; t++) {
        if (t == NTILES - 1) cp_wait0(); else cp_wait1();
        __syncwarp();

        const float* xb = xs_w + (t & 1) * STAGE_F;

        uint32_t ahi[4], alo[4];
        load_a_frag(xb, g, tg, ahi, alo);

        uint32_t bhi[2][2], blo[2][2];
#pragma unroll
        for (int nt = 0; nt < 2; nt++) {
            uint2 h = *(const uint2*)&sB[((t * 2 + 0) * 16 + nt * 8 + g) * 8 + 2 * tg];
            uint2 l = *(const uint2*)&sB[((t * 2 + 1) * 16 + nt * 8 + g) * 8 + 2 * tg];
            bhi[nt][0] = h.x; bhi[nt][1] = h.y;
            blo[nt][0] = l.x; blo[nt][1] = l.y;
        }

#pragma unroll
        for (int nt = 0; nt < 2; nt++) {
            mma_bf16(acc[nt], ahi, bhi[nt]);   // hi*hi
            mma_bf16(acc[nt], ahi, blo[nt]);   // hi*lo
            mma_bf16(acc[nt], alo, bhi[nt]);   // lo*hi
        }
        __syncwarp();

        if (t + 2 < NTILES)
            issue_tile(xs_s, xw, lane, t + 2, t & 1);
    }

    // ---- exchange D through warp-private smem: eb[row_local][j] ----
    float* eb_w = xs_w;   // 16*20 = 320 floats <= 640
#pragma unroll
    for (int nt = 0; nt < 2; nt++) {
        int j = nt * 8 + 2 * tg;
        *(float2*)(eb_w + g * PITCH + j)       = make_float2(acc[nt][0], acc[nt][1]);
        *(float2*)(eb_w + (g + 8) * PITCH + j) = make_float2(acc[nt][2], acc[nt][3]);
    }
    __syncwarp();

    // ---- epilogue: lanes 0..15 own one row each ----
    if (lane < ROWS_WARP) {
        const int row = warpRow0 + lane;
        float4 hv  = ((const float4*)hx)[row];
        float4 cxv = ((const float4*)cx)[row];
        const float4* hw4 = (const float4*)hwt;

        float z[NJ];
#pragma unroll
        for (int j = 0; j < NJ; j++) {
            float4 w = hw4[j];
            float ang = eb_w[lane * PITCH + j] + sphase[j]
                      + hv.x * w.x + hv.y * w.y + hv.z * w.z + hv.w * w.w;
            z[j] = __cosf(ang);
        }
        float e[NJ];
#pragma unroll
        for (int gg = 0; gg < 4; gg++) {
            float z0 = z[gg*4+0], z1 = z[gg*4+1], z2 = z[gg*4+2], z3 = z[gg*4+3];
            float p01 = z0 * z1;
            e[gg*4+0] = z1 * z2 * z3;
            e[gg*4+1] = p01;
            e[gg*4+2] = p01 * z2;
            e[gg*4+3] = p01 * z2 * z3;
        }
        float cxa[4] = {cxv.x, cxv.y, cxv.z, cxv.w};
        float hn[4], cn[4];
#pragma unroll
        for (int w = 0; w < 4; w++) {
            float fv = sigmoidf_(e[0*4+w]);
            float iv = sigmoidf_(e[1*4+w]);
            float gv = tanhf_(e[2*4+w]);
            float ov = sigmoidf_(e[3*4+w]);
            float c = fv * cxa[w] + iv * gv;
            cn[w] = c;
            hn[w] = ov * tanhf_(c);
        }
        ((float4*)out)[row] = make_float4(hn[0], hn[1], hn[2], hn[3]);
        ((float4*)(out + (size_t)B * 4))[row] = make_float4(cn[0], cn[1], cn[2], cn[3]);
    }
}

extern "C" void kernel_launch(void* const* d_in, const int* in_sizes, int n_in,
                              void* d_out, int out_size) {
    const float* x  = (const float*)d_in[0];
    const float* hx = (const float*)d_in[1];
    const float* cx = (const float*)d_in[2];
    const float* Wf = (const float*)d_in[3];
    const float* bf = (const float*)d_in[4];
    const float* Wi = (const float*)d_in[5];
    const float* bi = (const float*)d_in[6];
    const float* Wu = (const float*)d_in[7];
    const float* bu = (const float*)d_in[8];
    const float* Wo = (const float*)d_in[9];
    const float* bo = (const float*)d_in[10];
    const float* tf = (const float*)d_in[11];
    const float* ti = (const float*)d_in[12];
    const float* tu = (const float*)d_in[13];
    const float* to = (const float*)d_in[14];
    float* out = (float*)d_out;

    int B = in_sizes[0] / D_COLS;                 // 131072
    int grid = (B + ROWS_BLK - 1) / ROWS_BLK;     // 2048

    qlstm_mma_kernel<<<grid, THREADS>>>(x, hx, cx, Wf, Wi, Wu, Wo,
                                        bf, bi, bu, bo,
                                        tf, ti, tu, to, out, B);
}